// round 14
// baseline (speedup 1.0000x reference)
#include <cuda_runtime.h>
#include <cuda_bf16.h>
#include <math.h>

#define NN 100000
#define EE 3200000
#define NEMAX (EE + NN + 8 * NN)   // padded CSR (segments rounded up to 8)
#define GEMMB 782          // ceil(NN/128) gemm blocks (128 rows each)
#define CNTB 512           // count blocks (side stream, grid-stride)
#define PADT 130           // transposed-tile row pitch (even, low-conflict STS)

typedef unsigned long long ull;

// ---------------- scratch (device globals; no allocation allowed) ----------
// +1 sentinel row everywhere: node NN is the "dead" pad target.
__device__ __align__(16) float g_xp1[(NN + 1) * 32];  // row NN: never written = 0
__device__ float g_as1[(NN + 1) * 4];  // slot NN*4..+3 = -1e30 (set by alloc)
__device__ float g_ad1[NN * 4];
__device__ __align__(16) float g_xp2[(NN + 1) * 8];   // row NN: zeros
__device__ float g_as2[NN + 1];        // slot NN = -1e30 (set by alloc)
__device__ float g_ad2[NN];
__device__ int   g_deg[NN];
__device__ int   g_degP[NN];
__device__ int   g_off[NN];
__device__ int   g_pos[NN];
__device__ __align__(8) int g_csr[NEMAX];
__device__ int   g_total;

// ---------------- packed f32x2 helpers ------------------------------------
__device__ __forceinline__ ull dup2(float v) {
    ull r; unsigned u = __float_as_uint(v);
    asm("mov.b64 %0, {%1, %1};" : "=l"(r) : "r"(u));
    return r;
}
__device__ __forceinline__ ull fma2(ull a, ull b, ull c) {
    ull d;
    asm("fma.rn.f32x2 %0, %1, %2, %3;" : "=l"(d) : "l"(a), "l"(b), "l"(c));
    return d;
}
__device__ __forceinline__ void unpack2(ull v, float& lo, float& hi) {
    unsigned a, b;
    asm("mov.b64 {%0, %1}, %2;" : "=r"(a), "=r"(b) : "l"(v));
    lo = __uint_as_float(a); hi = __uint_as_float(b);
}

// ==== K1: f32x2 GEMM1 (128x32 tile, high-occupancy) + fused attn epilogue ===
__global__ __launch_bounds__(256) void k1_gemm(
    const float* __restrict__ x, const float* __restrict__ W,
    const float* __restrict__ as1, const float* __restrict__ ad1)
{
    __shared__ float xs[32 * PADT];            // [k][row] transposed, 128 rows
    __shared__ float ws[32 * 32];              // [k][col]
    int t = threadIdx.x;
    int row0 = blockIdx.x * 128;
    int rg  = t >> 3;                          // 0..31 -> rows rg*4..rg*4+3
    int cg4 = (t & 7) << 2;                    // 0,4,...,28 col base
    int kq  = (t & 7) << 2;                    // load: k-quad 0..28
    int rl  = t >> 3;                          // load: row 0..31 (+32*i)

    ull acc[2][4];
#pragma unroll
    for (int p = 0; p < 2; p++)
#pragma unroll
        for (int c = 0; c < 4; c++) acc[p][c] = 0ull;

    for (int kk = 0; kk < 512; kk += 32) {
        // load x tile transposed: 128 rows x 32 k (full coverage)
#pragma unroll
        for (int i = 0; i < 4; i++) {
            int row = rl + (i << 5);
            int grow = row0 + row;
            float4 v = make_float4(0.f, 0.f, 0.f, 0.f);
            if (grow < NN)
                v = *(const float4*)(x + (size_t)grow * 512 + kk + kq);
            xs[(kq + 0) * PADT + row] = v.x;
            xs[(kq + 1) * PADT + row] = v.y;
            xs[(kq + 2) * PADT + row] = v.z;
            xs[(kq + 3) * PADT + row] = v.w;
        }
        {   // load W tile [32 k][32 cols]
            int r = t >> 3, k4 = (t & 7) << 2;
            *(float4*)&ws[r * 32 + k4] = *(const float4*)(W + (size_t)(kk + r) * 32 + k4);
        }
        __syncthreads();
#pragma unroll
        for (int k = 0; k < 32; k++) {
            float4 wv = *(float4*)&ws[k * 32 + cg4];
            ull w0 = dup2(wv.x), w1 = dup2(wv.y), w2 = dup2(wv.z), w3 = dup2(wv.w);
            const ull* xr = (const ull*)&xs[k * PADT + (rg << 2)];
            ull x0 = xr[0], x1 = xr[1];
            acc[0][0] = fma2(x0, w0, acc[0][0]); acc[0][1] = fma2(x0, w1, acc[0][1]);
            acc[0][2] = fma2(x0, w2, acc[0][2]); acc[0][3] = fma2(x0, w3, acc[0][3]);
            acc[1][0] = fma2(x1, w0, acc[1][0]); acc[1][1] = fma2(x1, w1, acc[1][1]);
            acc[1][2] = fma2(x1, w2, acc[1][2]); acc[1][3] = fma2(x1, w3, acc[1][3]);
        }
        __syncthreads();
    }

    // epilogue: store xp1 + fused attention projections
    int head = cg4 >> 3;
    int half = (cg4 >> 2) & 1;
    float a_s[4], a_d[4];
#pragma unroll
    for (int c = 0; c < 4; c++) {
        a_s[c] = as1[head * 8 + half * 4 + c];
        a_d[c] = ad1[head * 8 + half * 4 + c];
    }
#pragma unroll
    for (int p = 0; p < 2; p++) {
        float o0[4], o1[4];
#pragma unroll
        for (int c = 0; c < 4; c++) unpack2(acc[p][c], o0[c], o1[c]);
#pragma unroll
        for (int rr = 0; rr < 2; rr++) {
            float* o = rr ? o1 : o0;
            int row = row0 + (rg << 2) + (p << 1) + rr;
            float sv = o[0]*a_s[0] + o[1]*a_s[1] + o[2]*a_s[2] + o[3]*a_s[3];
            float dv = o[0]*a_d[0] + o[1]*a_d[1] + o[2]*a_d[2] + o[3]*a_d[3];
            sv += __shfl_xor_sync(0xffffffffu, sv, 1);   // combine head halves
            dv += __shfl_xor_sync(0xffffffffu, dv, 1);
            if (row < NN) {
                *(float4*)(g_xp1 + (size_t)row * 32 + cg4) =
                    make_float4(o[0], o[1], o[2], o[3]);
                if (half == 0) g_as1[row * 4 + head] = sv;
                else           g_ad1[row * 4 + head] = dv;
            }
        }
    }
}

// ---------------- degree count (side stream) -------------------------------
__global__ void count_kernel(const int* __restrict__ dst, int E) {
    int i = blockIdx.x * blockDim.x + threadIdx.x;
    for (; i < E; i += CNTB * 256) atomicAdd(&g_deg[dst[i]], 1);
}

// ------ CSR alloc: pad segments to 8 with sentinel NN; reset g_deg ---------
__global__ void alloc_kernel() {
    int n = blockIdx.x * blockDim.x + threadIdx.x;
    int lane = threadIdx.x & 31;
    int deg = (n < NN) ? g_deg[n] + 1 : 0;
    int degP = (deg + 7) & ~7;
    int scan = degP;
#pragma unroll
    for (int d = 1; d < 32; d <<= 1) {
        int tv = __shfl_up_sync(0xffffffffu, scan, d);
        if (lane >= d) scan += tv;
    }
    int total = __shfl_sync(0xffffffffu, scan, 31);
    int base = 0;
    if (lane == 31) base = atomicAdd(&g_total, total);
    base = __shfl_sync(0xffffffffu, base, 31);
    int off = base + scan - degP;
    if (n == 0) {
        g_as1[NN * 4 + 0] = -1e30f; g_as1[NN * 4 + 1] = -1e30f;
        g_as1[NN * 4 + 2] = -1e30f; g_as1[NN * 4 + 3] = -1e30f;
        g_as2[NN] = -1e30f;
    }
    if (n < NN) {
        g_off[n]  = off;
        g_csr[off] = n;
        g_pos[n]  = off + 1;
        g_degP[n] = degP;
        for (int i = deg; i < degP; i++) g_csr[off + i] = NN;
        g_deg[n]  = 0;
    }
}

__global__ void scatter_kernel(const int* __restrict__ src,
                               const int* __restrict__ dst, int E) {
    if (blockIdx.x == 0 && threadIdx.x == 0) g_total = 0;
    int i = blockIdx.x * blockDim.x + threadIdx.x;
    if (i >= E) return;
    int d = dst[i];
    int slot = atomicAdd(&g_pos[d], 1);
    g_csr[slot] = src[i];
}

// == l1: zero-shuffle, predicate-free hot loop, fused ELU + xp2/as2/ad2 =====
__global__ __launch_bounds__(256) void l1_kernel(
    const float* __restrict__ b1, const float* __restrict__ W2,
    const float* __restrict__ as2v, const float* __restrict__ ad2v)
{
    __shared__ float W2s[256];
    __shared__ float hs[8][36];
    int t = threadIdx.x;
    W2s[t] = W2[t];
    __syncthreads();

    int wid = t >> 5, lane = t & 31;
    int n = blockIdx.x * 8 + wid;
    int off = g_off[n], degP = g_degP[n];
    int q  = lane >> 3;
    int c4 = lane & 7;
    int hc = c4 >> 1;
    float adh = g_ad1[n * 4 + hc];
    const float* xp1q = g_xp1 + (c4 << 2);
    const int* csrp = g_csr + off + (q << 1);

    float4 acc = make_float4(0.f, 0.f, 0.f, 0.f);
    float sum = 0.f;
#pragma unroll 2
    for (int base = 0; base < degP; base += 8) {
        int2 s2 = *(const int2*)(csrp + base);
        float vA = g_as1[s2.x * 4 + hc] + adh;
        float vB = g_as1[s2.y * 4 + hc] + adh;
        vA = fmaxf(vA, 0.2f * vA);
        vB = fmaxf(vB, 0.2f * vB);
        float pA = __expf(vA);
        float pB = __expf(vB);
        sum += pA + pB;
        float4 xa = *(const float4*)(xp1q + (size_t)s2.x * 32);
        float4 xb = *(const float4*)(xp1q + (size_t)s2.y * 32);
        acc.x = fmaf(pA, xa.x, fmaf(pB, xb.x, acc.x));
        acc.y = fmaf(pA, xa.y, fmaf(pB, xb.y, acc.y));
        acc.z = fmaf(pA, xa.z, fmaf(pB, xb.z, acc.z));
        acc.w = fmaf(pA, xa.w, fmaf(pB, xb.w, acc.w));
    }
    sum   += __shfl_xor_sync(0xffffffffu, sum, 8);
    acc.x += __shfl_xor_sync(0xffffffffu, acc.x, 8);
    acc.y += __shfl_xor_sync(0xffffffffu, acc.y, 8);
    acc.z += __shfl_xor_sync(0xffffffffu, acc.z, 8);
    acc.w += __shfl_xor_sync(0xffffffffu, acc.w, 8);
    sum   += __shfl_xor_sync(0xffffffffu, sum, 16);
    acc.x += __shfl_xor_sync(0xffffffffu, acc.x, 16);
    acc.y += __shfl_xor_sync(0xffffffffu, acc.y, 16);
    acc.z += __shfl_xor_sync(0xffffffffu, acc.z, 16);
    acc.w += __shfl_xor_sync(0xffffffffu, acc.w, 16);
    float invd = 1.f / sum;

    if (q == 0) {
        float4 bv = *(const float4*)(b1 + (c4 << 2));
        float o0 = fmaf(acc.x, invd, bv.x);
        float o1 = fmaf(acc.y, invd, bv.y);
        float o2 = fmaf(acc.z, invd, bv.z);
        float o3 = fmaf(acc.w, invd, bv.w);
        o0 = o0 > 0.f ? o0 : expm1f(o0);
        o1 = o1 > 0.f ? o1 : expm1f(o1);
        o2 = o2 > 0.f ? o2 : expm1f(o2);
        o3 = o3 > 0.f ? o3 : expm1f(o3);
        *(float4*)&hs[wid][c4 << 2] = make_float4(o0, o1, o2, o3);
    }
    __syncwarp();

    if (lane < 8) {
        float s2 = 0.f;
#pragma unroll
        for (int k2 = 0; k2 < 32; k2++)
            s2 = fmaf(hs[wid][k2], W2s[k2 * 8 + lane], s2);
        g_xp2[(size_t)n * 8 + lane] = s2;
        float a = s2 * as2v[lane], d = s2 * ad2v[lane];
        a += __shfl_xor_sync(0xffu, a, 1);
        a += __shfl_xor_sync(0xffu, a, 2);
        a += __shfl_xor_sync(0xffu, a, 4);
        d += __shfl_xor_sync(0xffu, d, 1);
        d += __shfl_xor_sync(0xffu, d, 2);
        d += __shfl_xor_sync(0xffu, d, 4);
        if (lane == 0) { g_as2[n] = a; g_ad2[n] = d; }
    }
}

// ========== l2: zero-shuffle, predicate-free hot loop ======================
__global__ __launch_bounds__(256) void l2_kernel(float* __restrict__ out,
                                                 const float* __restrict__ b2)
{
    int t = threadIdx.x, wid = t >> 5, lane = t & 31;
    int n = blockIdx.x * 8 + wid;
    int off = g_off[n], degP = g_degP[n];
    int j8 = lane >> 2, c2 = lane & 3;
    float adn = g_ad2[n];
    const float* xp2p = g_xp2 + (c2 << 1);

    float2 acc = make_float2(0.f, 0.f);
    float sum = 0.f;
#pragma unroll 2
    for (int base = 0; base < degP; base += 8) {
        int sv = g_csr[off + base + j8];
        float v = g_as2[sv] + adn;
        v = fmaxf(v, 0.2f * v);
        float p = __expf(v);
        sum += p;
        float2 xv = *(const float2*)(xp2p + (size_t)sv * 8);
        acc.x = fmaf(p, xv.x, acc.x);
        acc.y = fmaf(p, xv.y, acc.y);
    }
    sum   += __shfl_xor_sync(0xffffffffu, sum, 4);
    acc.x += __shfl_xor_sync(0xffffffffu, acc.x, 4);
    acc.y += __shfl_xor_sync(0xffffffffu, acc.y, 4);
    sum   += __shfl_xor_sync(0xffffffffu, sum, 8);
    acc.x += __shfl_xor_sync(0xffffffffu, acc.x, 8);
    acc.y += __shfl_xor_sync(0xffffffffu, acc.y, 8);
    sum   += __shfl_xor_sync(0xffffffffu, sum, 16);
    acc.x += __shfl_xor_sync(0xffffffffu, acc.x, 16);
    acc.y += __shfl_xor_sync(0xffffffffu, acc.y, 16);
    float invd = 1.f / sum;
    if (lane < 4) {
        float2 bv = *(const float2*)(b2 + (c2 << 1));
        float2 ov;
        ov.x = fmaf(acc.x, invd, bv.x);
        ov.y = fmaf(acc.y, invd, bv.y);
        *(float2*)(out + (size_t)n * 8 + (c2 << 1)) = ov;
    }
}

// ---------------------------------------------------------------------------
extern "C" void kernel_launch(void* const* d_in, const int* in_sizes, int n_in,
                              void* d_out, int out_size) {
    const float* x        = (const float*)d_in[0];
    const int*   eidx     = (const int*)d_in[1];
    const float* W1       = (const float*)d_in[2];
    const float* att_src1 = (const float*)d_in[3];
    const float* att_dst1 = (const float*)d_in[4];
    const float* b1       = (const float*)d_in[5];
    const float* W2       = (const float*)d_in[6];
    const float* att_src2 = (const float*)d_in[7];
    const float* att_dst2 = (const float*)d_in[8];
    const float* b2       = (const float*)d_in[9];
    float* out = (float*)d_out;

    int E = in_sizes[1] / 2;
    const int* src = eidx;
    const int* dst = eidx + E;

    static cudaStream_t s2 = nullptr;
    static cudaEvent_t ev_root = nullptr, ev_csr = nullptr;
    if (s2 == nullptr) {
        cudaStreamCreateWithFlags(&s2, cudaStreamNonBlocking);
        cudaEventCreateWithFlags(&ev_root, cudaEventDisableTiming);
        cudaEventCreateWithFlags(&ev_csr, cudaEventDisableTiming);
    }

    // fork: CSR chain on s2, GEMM on the captured (default) stream
    cudaEventRecord(ev_root, 0);
    cudaStreamWaitEvent(s2, ev_root, 0);
    count_kernel<<<CNTB, 256, 0, s2>>>(dst, E);
    alloc_kernel<<<(NN + 255) / 256, 256, 0, s2>>>();
    scatter_kernel<<<(E + 255) / 256, 256, 0, s2>>>(src, dst, E);
    cudaEventRecord(ev_csr, s2);

    k1_gemm<<<GEMMB, 256>>>(x, W1, att_src1, att_dst1);

    cudaStreamWaitEvent(0, ev_csr, 0);
    l1_kernel<<<NN / 8, 256>>>(b1, W2, att_src2, att_dst2);
    l2_kernel<<<NN / 8, 256>>>(out, b2);
}

// round 15
// speedup vs baseline: 1.1197x; 1.1197x over previous
#include <cuda_runtime.h>
#include <cuda_bf16.h>
#include <math.h>
#include <stdint.h>

#define NN 100000
#define EE 3200000
#define NEMAX (EE + NN + 8 * NN)   // padded CSR (segments rounded up to 8)
#define GEMMB 782          // ceil(NN/128) gemm blocks (128 rows each)
#define CNTB 512           // count blocks (side stream, grid-stride)

// ---------------- scratch (device globals; no allocation allowed) ----------
// +1 sentinel row everywhere: node NN is the "dead" pad target.
__device__ __align__(16) float g_xp1[(NN + 1) * 32];  // row NN: never written = 0
__device__ float g_as1[(NN + 1) * 4];  // slot NN*4..+3 = -1e30 (set by alloc)
__device__ float g_ad1[NN * 4];
__device__ __align__(16) float g_xp2[(NN + 1) * 8];   // row NN: zeros
__device__ float g_as2[NN + 1];        // slot NN = -1e30 (set by alloc)
__device__ float g_ad2[NN];
__device__ int   g_deg[NN];
__device__ int   g_degP[NN];
__device__ int   g_off[NN];
__device__ int   g_pos[NN];
__device__ __align__(8) int g_csr[NEMAX];
__device__ int   g_total;

// ---------------- bf16 split helpers ---------------------------------------
// pack_bf(lo, hi): bf16x2 with low half = lo element (k even), high = hi (k odd)
__device__ __forceinline__ uint32_t pack_bf(float lo, float hi) {
    uint32_t r;
    asm("cvt.rn.bf16x2.f32 %0, %1, %2;" : "=r"(r) : "f"(hi), "f"(lo));
    return r;
}
__device__ __forceinline__ float bf_lo_f32(uint32_t p) {
    return __uint_as_float(p << 16);
}
__device__ __forceinline__ float bf_hi_f32(uint32_t p) {
    return __uint_as_float(p & 0xffff0000u);
}
// hi/lo split of a k-pair (v0 = even k, v1 = odd k)
__device__ __forceinline__ void split_pair(float v0, float v1,
                                           uint32_t& hp, uint32_t& lp) {
    hp = pack_bf(v0, v1);
    lp = pack_bf(v0 - bf_lo_f32(hp), v1 - bf_hi_f32(hp));
}
__device__ __forceinline__ void mma_bf16(float* d, const uint32_t* a,
                                         uint32_t b0, uint32_t b1) {
    asm volatile(
        "mma.sync.aligned.m16n8k16.row.col.f32.bf16.bf16.f32 "
        "{%0,%1,%2,%3}, {%4,%5,%6,%7}, {%8,%9}, {%0,%1,%2,%3};"
        : "+f"(d[0]), "+f"(d[1]), "+f"(d[2]), "+f"(d[3])
        : "r"(a[0]), "r"(a[1]), "r"(a[2]), "r"(a[3]), "r"(b0), "r"(b1));
}

// ==== K1: bf16-split HMMA GEMM1 (128x32 tile) + fused attn epilogue ========
// K streamed in 32 chunks of 16. A/B in smem as packed bf16x2 k-pairs,
// pitch 12 u32 per row (conflict-free for the g*12+tig fragment reads).
__global__ __launch_bounds__(256) void k1_gemm(
    const float* __restrict__ x, const float* __restrict__ W,
    const float* __restrict__ as1, const float* __restrict__ ad1)
{
    __shared__ uint32_t Ahi[128 * 12], Alo[128 * 12];
    __shared__ uint32_t Bhi[32 * 12],  Blo[32 * 12];
    __shared__ float atts[32], attd[32];
    int t = threadIdx.x, w = t >> 5, lane = t & 31;
    int g = lane >> 2, tig = lane & 3;
    int row0 = blockIdx.x * 128;

    if (t < 32)       atts[t] = as1[t];
    else if (t < 64)  attd[t - 32] = ad1[t - 32];

    float acc[4][4];
#pragma unroll
    for (int nt = 0; nt < 4; nt++)
#pragma unroll
        for (int i = 0; i < 4; i++) acc[nt][i] = 0.f;

    // conversion mapping: A: thread -> row t>>1, k-octet (t&1)*8
    int arow = t >> 1, akoff = (t & 1) << 3;
    int agrow = row0 + arow;
    const float* axp = x + (size_t)agrow * 512 + akoff;
    // B: thread -> n = t&31, k-pair jp = t>>5
    int bn = t & 31, bjp = t >> 5;

    for (int ch = 0; ch < 32; ch++) {
        int k0 = ch << 4;
        // ---- convert A (128 rows x 16 k) ----
        float4 v0 = make_float4(0.f, 0.f, 0.f, 0.f), v1 = v0;
        if (agrow < NN) {
            v0 = *(const float4*)(axp + k0);
            v1 = *(const float4*)(axp + k0 + 4);
        }
        uint32_t h[4], l[4];
        split_pair(v0.x, v0.y, h[0], l[0]);
        split_pair(v0.z, v0.w, h[1], l[1]);
        split_pair(v1.x, v1.y, h[2], l[2]);
        split_pair(v1.z, v1.w, h[3], l[3]);
        {
            int c0 = arow * 12 + ((t & 1) << 2);
            *(uint4*)&Ahi[c0] = make_uint4(h[0], h[1], h[2], h[3]);
            *(uint4*)&Alo[c0] = make_uint4(l[0], l[1], l[2], l[3]);
        }
        // ---- convert B (16 k x 32 n) ----
        {
            float w0 = W[(size_t)(k0 + (bjp << 1)) * 32 + bn];
            float w1 = W[(size_t)(k0 + (bjp << 1) + 1) * 32 + bn];
            uint32_t hp, lp;
            split_pair(w0, w1, hp, lp);
            Bhi[bn * 12 + bjp] = hp;
            Blo[bn * 12 + bjp] = lp;
        }
        __syncthreads();
        // ---- fragments ----
        uint32_t ah[4], al[4];
        {
            int r0 = ((w << 4) + g) * 12, r1 = ((w << 4) + g + 8) * 12;
            ah[0] = Ahi[r0 + tig];     ah[1] = Ahi[r1 + tig];
            ah[2] = Ahi[r0 + tig + 4]; ah[3] = Ahi[r1 + tig + 4];
            al[0] = Alo[r0 + tig];     al[1] = Alo[r1 + tig];
            al[2] = Alo[r0 + tig + 4]; al[3] = Alo[r1 + tig + 4];
        }
#pragma unroll
        for (int nt = 0; nt < 4; nt++) {
            int bb = ((nt << 3) + g) * 12;
            uint32_t b0h = Bhi[bb + tig], b1h = Bhi[bb + tig + 4];
            uint32_t b0l = Blo[bb + tig], b1l = Blo[bb + tig + 4];
            mma_bf16(acc[nt], ah, b0h, b1h);
            mma_bf16(acc[nt], ah, b0l, b1l);
            mma_bf16(acc[nt], al, b0h, b1h);
        }
        __syncthreads();
    }

    // ---- epilogue: xp1 + fused attention projections ----
    int r0 = row0 + (w << 4) + g;
    int r1 = r0 + 8;
#pragma unroll
    for (int nt = 0; nt < 4; nt++) {
        int c = (nt << 3) + (tig << 1);
        float a_s0 = atts[c], a_s1 = atts[c + 1];
        float a_d0 = attd[c], a_d1 = attd[c + 1];
        float sv0 = acc[nt][0] * a_s0 + acc[nt][1] * a_s1;
        float dv0 = acc[nt][0] * a_d0 + acc[nt][1] * a_d1;
        float sv1 = acc[nt][2] * a_s0 + acc[nt][3] * a_s1;
        float dv1 = acc[nt][2] * a_d0 + acc[nt][3] * a_d1;
        sv0 += __shfl_xor_sync(0xffffffffu, sv0, 1);
        sv0 += __shfl_xor_sync(0xffffffffu, sv0, 2);
        dv0 += __shfl_xor_sync(0xffffffffu, dv0, 1);
        dv0 += __shfl_xor_sync(0xffffffffu, dv0, 2);
        sv1 += __shfl_xor_sync(0xffffffffu, sv1, 1);
        sv1 += __shfl_xor_sync(0xffffffffu, sv1, 2);
        dv1 += __shfl_xor_sync(0xffffffffu, dv1, 1);
        dv1 += __shfl_xor_sync(0xffffffffu, dv1, 2);
        if (r0 < NN)
            *(float2*)(g_xp1 + (size_t)r0 * 32 + c) =
                make_float2(acc[nt][0], acc[nt][1]);
        if (r1 < NN)
            *(float2*)(g_xp1 + (size_t)r1 * 32 + c) =
                make_float2(acc[nt][2], acc[nt][3]);
        if (tig == 0) {
            if (r0 < NN) { g_as1[r0 * 4 + nt] = sv0; g_ad1[r0 * 4 + nt] = dv0; }
            if (r1 < NN) { g_as1[r1 * 4 + nt] = sv1; g_ad1[r1 * 4 + nt] = dv1; }
        }
    }
}

// ---------------- degree count (side stream) -------------------------------
__global__ void count_kernel(const int* __restrict__ dst, int E) {
    int i = blockIdx.x * blockDim.x + threadIdx.x;
    for (; i < E; i += CNTB * 256) atomicAdd(&g_deg[dst[i]], 1);
}

// ------ CSR alloc: pad segments to 8 with sentinel NN; reset g_deg ---------
__global__ void alloc_kernel() {
    int n = blockIdx.x * blockDim.x + threadIdx.x;
    int lane = threadIdx.x & 31;
    int deg = (n < NN) ? g_deg[n] + 1 : 0;
    int degP = (deg + 7) & ~7;
    int scan = degP;
#pragma unroll
    for (int d = 1; d < 32; d <<= 1) {
        int tv = __shfl_up_sync(0xffffffffu, scan, d);
        if (lane >= d) scan += tv;
    }
    int total = __shfl_sync(0xffffffffu, scan, 31);
    int base = 0;
    if (lane == 31) base = atomicAdd(&g_total, total);
    base = __shfl_sync(0xffffffffu, base, 31);
    int off = base + scan - degP;
    if (n == 0) {
        g_as1[NN * 4 + 0] = -1e30f; g_as1[NN * 4 + 1] = -1e30f;
        g_as1[NN * 4 + 2] = -1e30f; g_as1[NN * 4 + 3] = -1e30f;
        g_as2[NN] = -1e30f;
    }
    if (n < NN) {
        g_off[n]  = off;
        g_csr[off] = n;
        g_pos[n]  = off + 1;
        g_degP[n] = degP;
        for (int i = deg; i < degP; i++) g_csr[off + i] = NN;
        g_deg[n]  = 0;
    }
}

__global__ void scatter_kernel(const int* __restrict__ src,
                               const int* __restrict__ dst, int E) {
    if (blockIdx.x == 0 && threadIdx.x == 0) g_total = 0;
    int i = blockIdx.x * blockDim.x + threadIdx.x;
    if (i >= E) return;
    int d = dst[i];
    int slot = atomicAdd(&g_pos[d], 1);
    g_csr[slot] = src[i];
}

// == l1: zero-shuffle, predicate-free hot loop, fused ELU + xp2/as2/ad2 =====
__global__ __launch_bounds__(256) void l1_kernel(
    const float* __restrict__ b1, const float* __restrict__ W2,
    const float* __restrict__ as2v, const float* __restrict__ ad2v)
{
    __shared__ float W2s[256];
    __shared__ float hs[8][36];
    int t = threadIdx.x;
    W2s[t] = W2[t];
    __syncthreads();

    int wid = t >> 5, lane = t & 31;
    int n = blockIdx.x * 8 + wid;
    int off = g_off[n], degP = g_degP[n];
    int q  = lane >> 3;
    int c4 = lane & 7;
    int hc = c4 >> 1;
    float adh = g_ad1[n * 4 + hc];
    const float* xp1q = g_xp1 + (c4 << 2);
    const int* csrp = g_csr + off + (q << 1);

    float4 acc = make_float4(0.f, 0.f, 0.f, 0.f);
    float sum = 0.f;
#pragma unroll 2
    for (int base = 0; base < degP; base += 8) {
        int2 s2 = *(const int2*)(csrp + base);
        float vA = g_as1[s2.x * 4 + hc] + adh;
        float vB = g_as1[s2.y * 4 + hc] + adh;
        vA = fmaxf(vA, 0.2f * vA);
        vB = fmaxf(vB, 0.2f * vB);
        float pA = __expf(vA);
        float pB = __expf(vB);
        sum += pA + pB;
        float4 xa = *(const float4*)(xp1q + (size_t)s2.x * 32);
        float4 xb = *(const float4*)(xp1q + (size_t)s2.y * 32);
        acc.x = fmaf(pA, xa.x, fmaf(pB, xb.x, acc.x));
        acc.y = fmaf(pA, xa.y, fmaf(pB, xb.y, acc.y));
        acc.z = fmaf(pA, xa.z, fmaf(pB, xb.z, acc.z));
        acc.w = fmaf(pA, xa.w, fmaf(pB, xb.w, acc.w));
    }
    sum   += __shfl_xor_sync(0xffffffffu, sum, 8);
    acc.x += __shfl_xor_sync(0xffffffffu, acc.x, 8);
    acc.y += __shfl_xor_sync(0xffffffffu, acc.y, 8);
    acc.z += __shfl_xor_sync(0xffffffffu, acc.z, 8);
    acc.w += __shfl_xor_sync(0xffffffffu, acc.w, 8);
    sum   += __shfl_xor_sync(0xffffffffu, sum, 16);
    acc.x += __shfl_xor_sync(0xffffffffu, acc.x, 16);
    acc.y += __shfl_xor_sync(0xffffffffu, acc.y, 16);
    acc.z += __shfl_xor_sync(0xffffffffu, acc.z, 16);
    acc.w += __shfl_xor_sync(0xffffffffu, acc.w, 16);
    float invd = 1.f / sum;

    if (q == 0) {
        float4 bv = *(const float4*)(b1 + (c4 << 2));
        float o0 = fmaf(acc.x, invd, bv.x);
        float o1 = fmaf(acc.y, invd, bv.y);
        float o2 = fmaf(acc.z, invd, bv.z);
        float o3 = fmaf(acc.w, invd, bv.w);
        o0 = o0 > 0.f ? o0 : expm1f(o0);
        o1 = o1 > 0.f ? o1 : expm1f(o1);
        o2 = o2 > 0.f ? o2 : expm1f(o2);
        o3 = o3 > 0.f ? o3 : expm1f(o3);
        *(float4*)&hs[wid][c4 << 2] = make_float4(o0, o1, o2, o3);
    }
    __syncwarp();

    if (lane < 8) {
        float s2 = 0.f;
#pragma unroll
        for (int k2 = 0; k2 < 32; k2++)
            s2 = fmaf(hs[wid][k2], W2s[k2 * 8 + lane], s2);
        g_xp2[(size_t)n * 8 + lane] = s2;
        float a = s2 * as2v[lane], d = s2 * ad2v[lane];
        a += __shfl_xor_sync(0xffu, a, 1);
        a += __shfl_xor_sync(0xffu, a, 2);
        a += __shfl_xor_sync(0xffu, a, 4);
        d += __shfl_xor_sync(0xffu, d, 1);
        d += __shfl_xor_sync(0xffu, d, 2);
        d += __shfl_xor_sync(0xffu, d, 4);
        if (lane == 0) { g_as2[n] = a; g_ad2[n] = d; }
    }
}

// ========== l2: zero-shuffle, predicate-free hot loop ======================
__global__ __launch_bounds__(256) void l2_kernel(float* __restrict__ out,
                                                 const float* __restrict__ b2)
{
    int t = threadIdx.x, wid = t >> 5, lane = t & 31;
    int n = blockIdx.x * 8 + wid;
    int off = g_off[n], degP = g_degP[n];
    int j8 = lane >> 2, c2 = lane & 3;
    float adn = g_ad2[n];
    const float* xp2p = g_xp2 + (c2 << 1);

    float2 acc = make_float2(0.f, 0.f);
    float sum = 0.f;
#pragma unroll 2
    for (int base = 0; base < degP; base += 8) {
        int sv = g_csr[off + base + j8];
        float v = g_as2[sv] + adn;
        v = fmaxf(v, 0.2f * v);
        float p = __expf(v);
        sum += p;
        float2 xv = *(const float2*)(xp2p + (size_t)sv * 8);
        acc.x = fmaf(p, xv.x, acc.x);
        acc.y = fmaf(p, xv.y, acc.y);
    }
    sum   += __shfl_xor_sync(0xffffffffu, sum, 4);
    acc.x += __shfl_xor_sync(0xffffffffu, acc.x, 4);
    acc.y += __shfl_xor_sync(0xffffffffu, acc.y, 4);
    sum   += __shfl_xor_sync(0xffffffffu, sum, 8);
    acc.x += __shfl_xor_sync(0xffffffffu, acc.x, 8);
    acc.y += __shfl_xor_sync(0xffffffffu, acc.y, 8);
    sum   += __shfl_xor_sync(0xffffffffu, sum, 16);
    acc.x += __shfl_xor_sync(0xffffffffu, acc.x, 16);
    acc.y += __shfl_xor_sync(0xffffffffu, acc.y, 16);
    float invd = 1.f / sum;
    if (lane < 4) {
        float2 bv = *(const float2*)(b2 + (c2 << 1));
        float2 ov;
        ov.x = fmaf(acc.x, invd, bv.x);
        ov.y = fmaf(acc.y, invd, bv.y);
        *(float2*)(out + (size_t)n * 8 + (c2 << 1)) = ov;
    }
}

// ---------------------------------------------------------------------------
extern "C" void kernel_launch(void* const* d_in, const int* in_sizes, int n_in,
                              void* d_out, int out_size) {
    const float* x        = (const float*)d_in[0];
    const int*   eidx     = (const int*)d_in[1];
    const float* W1       = (const float*)d_in[2];
    const float* att_src1 = (const float*)d_in[3];
    const float* att_dst1 = (const float*)d_in[4];
    const float* b1       = (const float*)d_in[5];
    const float* W2       = (const float*)d_in[6];
    const float* att_src2 = (const float*)d_in[7];
    const float* att_dst2 = (const float*)d_in[8];
    const float* b2       = (const float*)d_in[9];
    float* out = (float*)d_out;

    int E = in_sizes[1] / 2;
    const int* src = eidx;
    const int* dst = eidx + E;

    static cudaStream_t s2 = nullptr;
    static cudaEvent_t ev_root = nullptr, ev_csr = nullptr;
    if (s2 == nullptr) {
        cudaStreamCreateWithFlags(&s2, cudaStreamNonBlocking);
        cudaEventCreateWithFlags(&ev_root, cudaEventDisableTiming);
        cudaEventCreateWithFlags(&ev_csr, cudaEventDisableTiming);
    }

    // fork: CSR chain on s2, GEMM on the captured (default) stream
    cudaEventRecord(ev_root, 0);
    cudaStreamWaitEvent(s2, ev_root, 0);
    count_kernel<<<CNTB, 256, 0, s2>>>(dst, E);
    alloc_kernel<<<(NN + 255) / 256, 256, 0, s2>>>();
    scatter_kernel<<<(E + 255) / 256, 256, 0, s2>>>(src, dst, E);
    cudaEventRecord(ev_csr, s2);

    k1_gemm<<<GEMMB, 256>>>(x, W1, att_src1, att_dst1);

    cudaStreamWaitEvent(0, ev_csr, 0);
    l1_kernel<<<NN / 8, 256>>>(b1, W2, att_src2, att_dst2);
    l2_kernel<<<NN / 8, 256>>>(out, b2);
}